// round 7
// baseline (speedup 1.0000x reference)
#include <cuda_runtime.h>

// Inverse 2D DWT, single level. (4,64,256,256) f32 x4 subbands -> (4,64,512,512) f32.
// Warp-autonomous: one warp owns a 64-col strip x RW rows; each lane owns 2 adjacent
// columns. Processes 4 rows per iteration with a 6-row register window; ALL 32 loads
// for the NEXT iteration (16 LDG.64 owned + 16 scalar halo) are front-batched at the
// iteration top -> ~32 loads in flight per warp, load-use distance ~1 full iteration.
// Halo columns stay scalar until use. Streaming cache hints. No smem, no barriers.

#define HH 256
#define WW 256
#define RW 32
#define NT 128

typedef unsigned long long u64;

__device__ __forceinline__ u64 pk(float lo, float hi) {
    u64 r; asm("mov.b64 %0, {%1, %2};" : "=l"(r) : "f"(lo), "f"(hi)); return r;
}
__device__ __forceinline__ void unpk(u64 v, float& lo, float& hi) {
    asm("mov.b64 {%0, %1}, %2;" : "=f"(lo), "=f"(hi) : "l"(v));
}
__device__ __forceinline__ float lof(u64 v) { float a, b; unpk(v, a, b); return a; }
__device__ __forceinline__ float hif(u64 v) { float a, b; unpk(v, a, b); return b; }
__device__ __forceinline__ u64 ffma2(u64 a, u64 b, u64 c) {
    u64 d; asm("fma.rn.f32x2 %0, %1, %2, %3;" : "=l"(d) : "l"(a), "l"(b), "l"(c)); return d;
}
__device__ __forceinline__ u64 fmul2(u64 a, u64 b) {
    u64 d; asm("mul.rn.f32x2 %0, %1, %2;" : "=l"(d) : "l"(a), "l"(b)); return d;
}
__device__ __forceinline__ int reflH(int i) {
    return i < 0 ? -i : (i >= HH ? 2 * HH - 2 - i : i);
}
__device__ __forceinline__ float shup(float v) { return __shfl_up_sync(0xffffffffu, v, 1); }
__device__ __forceinline__ float shdn(float v) { return __shfl_down_sync(0xffffffffu, v, 1); }
__device__ __forceinline__ u64 ldg2(const float* __restrict__ p, int row) {
    return __ldcs((const unsigned long long*)(p + (size_t)row * WW));
}
__device__ __forceinline__ float ldg1(const float* __restrict__ p, int row, int dq) {
    return __ldcs(p + (size_t)row * WW + dq);
}

__global__ __launch_bounds__(NT, 3)
void idwt2d(const float* __restrict__ ss, const float* __restrict__ sd,
            const float* __restrict__ ds, const float* __restrict__ dd,
            const float* __restrict__ hf, const float* __restrict__ gf,
            float* __restrict__ out)
{
    const int lane = threadIdx.x & 31;
    const int wid  = threadIdx.x >> 5;     // strip index 0..3
    const int bc   = blockIdx.z;
    const int r0   = blockIdx.y * RW;
    const int wb   = 64 * wid;
    const int c    = wb + 2 * lane;

    // halo column (W-reflection built in): lanes 0-30 -> col wb-1 (broadcast), lane 31 -> col wb+64
    const int hcol = (lane == 31) ? ((wb + 64 < WW) ? wb + 64 : WW - 2)
                                  : ((wb > 0) ? wb - 1 : 1);
    const int dq = hcol - c;

    const size_t base = (size_t)bc * (HH * WW);
    const float* __restrict__ pss = ss + base + c;
    const float* __restrict__ psd = sd + base + c;
    const float* __restrict__ pds = ds + base + c;
    const float* __restrict__ pdd = dd + base + c;
    float* __restrict__ pout = out + (size_t)bc * (4 * HH * WW) + 2 * c;

    u64 H0, H1, H2, H3, H4, H5, G0, G1, G2, G3, G4, G5;
    {
        const float a0 = hf[0], a1 = hf[1], a2 = hf[2], a3 = hf[3], a4 = hf[4], a5 = hf[5];
        const float b0 = gf[0], b1 = gf[1], b2 = gf[2], b3 = gf[3], b4 = gf[4], b5 = gf[5];
        H0 = pk(a0, a0); H1 = pk(a1, a1); H2 = pk(a2, a2);
        H3 = pk(a3, a3); H4 = pk(a4, a4); H5 = pk(a5, a5);
        G0 = pk(b0, b0); G1 = pk(b1, b1); G2 = pk(b2, b2);
        G3 = pk(b3, b3); G4 = pk(b4, b4); G5 = pk(b5, b5);
    }

    // 6-row window: rows r-1 .. r+4 in slots 0..5 (owned f32x2 + scalar halo)
    u64 WS[6], WT[6], WU[6], WV[6];
    float HS[6], HT[6], HU[6], HV[6];
    #pragma unroll
    for (int k = 0; k < 6; ++k) {
        const int rr = reflH(r0 - 1 + k);
        WS[k] = ldg2(pss, rr); WT[k] = ldg2(psd, rr);
        WU[k] = ldg2(pds, rr); WV[k] = ldg2(pdd, rr);
        HS[k] = ldg1(pss, rr, dq); HT[k] = ldg1(psd, rr, dq);
        HU[k] = ldg1(pds, rr, dq); HV[k] = ldg1(pdd, rr, dq);
    }

    #pragma unroll 1
    for (int i = 0; i < RW; i += 4) {
        const int r = r0 + i;

        // ---- front-batched prefetch for NEXT iteration: rows r+5 .. r+8 ----
        u64 PS[4], PT[4], PU[4], PV[4];
        float QS[4], QT[4], QU[4], QV[4];
        #pragma unroll
        for (int k = 0; k < 4; ++k) {
            const int rr = reflH(r + 5 + k);
            PS[k] = ldg2(pss, rr); PT[k] = ldg2(psd, rr);
            PU[k] = ldg2(pds, rr); PV[k] = ldg2(pdd, rr);
            QS[k] = ldg1(pss, rr, dq); QT[k] = ldg1(psd, rr, dq);
            QU[k] = ldg1(pds, rr, dq); QV[k] = ldg1(pdd, rr, dq);
        }

        // ---- compute 4 owned rows from the current window ----
        #pragma unroll
        for (int k = 0; k < 4; ++k) {
            // column pass (f32x2, both owned columns)
            const u64 A0 = ffma2(H4, WS[k], ffma2(H2, WS[k+1], ffma2(H0, WS[k+2],
                           ffma2(G4, WT[k], ffma2(G2, WT[k+1], fmul2(G0, WT[k+2]))))));
            const u64 A1 = ffma2(H5, WS[k], ffma2(H3, WS[k+1], ffma2(H1, WS[k+2],
                           ffma2(G5, WT[k], ffma2(G3, WT[k+1], fmul2(G1, WT[k+2]))))));
            const u64 A2 = ffma2(H4, WU[k], ffma2(H2, WU[k+1], ffma2(H0, WU[k+2],
                           ffma2(G4, WV[k], ffma2(G2, WV[k+1], fmul2(G0, WV[k+2]))))));
            const u64 A3 = ffma2(H5, WU[k], ffma2(H3, WU[k+1], ffma2(H1, WU[k+2],
                           ffma2(G5, WV[k], ffma2(G3, WV[k+1], fmul2(G1, WV[k+2]))))));

            // halo column pass: pack at use (lo = s-side, hi = d-side)
            const u64 P0 = pk(HS[k],   HU[k]),   Q0 = pk(HT[k],   HV[k]);
            const u64 P1 = pk(HS[k+1], HU[k+1]), Q1 = pk(HT[k+1], HV[k+1]);
            const u64 P2 = pk(HS[k+2], HU[k+2]), Q2 = pk(HT[k+2], HV[k+2]);
            const u64 B02 = ffma2(H4, P0, ffma2(H2, P1, ffma2(H0, P2,
                            ffma2(G4, Q0, ffma2(G2, Q1, fmul2(G0, Q2))))));  // (b0,b2)
            const u64 B13 = ffma2(H5, P0, ffma2(H3, P1, ffma2(H1, P2,
                            ffma2(G5, Q0, ffma2(G3, Q1, fmul2(G1, Q2))))));  // (b1,b3)

            // row pass
            #pragma unroll
            for (int py = 0; py < 2; ++py) {
                const u64 X = py ? A1 : A0;
                const u64 Y = py ? A3 : A2;
                const u64 B = py ? B13 : B02;
                const float hx = lof(B), hy = hif(B);

                float xm = shup(hif(X)); if (lane == 0)  xm = hx;   // v[c-1]
                float xp = shdn(lof(X)); if (lane == 31) xp = hx;   // v[c+2]
                float ym = shup(hif(Y)); if (lane == 0)  ym = hy;
                float yp = shdn(lof(Y)); if (lane == 31) yp = hy;

                const u64 AX = pk(xm, lof(X)), CX = pk(hif(X), xp);
                const u64 AY = pk(ym, lof(Y)), CY = pk(hif(Y), yp);

                const u64 pe = ffma2(H4, AX, ffma2(H2, X, ffma2(H0, CX,
                               ffma2(G4, AY, ffma2(G2, Y, fmul2(G0, CY))))));
                const u64 po = ffma2(H5, AX, ffma2(H3, X, ffma2(H1, CX,
                               ffma2(G5, AY, ffma2(G3, Y, fmul2(G1, CY))))));

                float e0, e1, f0, f1;
                unpk(pe, e0, e1); unpk(po, f0, f1);
                __stcs((float4*)(pout + (size_t)(2 * (r + k) + py) * (2 * WW)),
                       make_float4(e0, f0, e1, f1));
            }
        }

        // ---- roll window by 4 rows; prefetched rows land in slots 2..5 ----
        WS[0] = WS[4]; WS[1] = WS[5];
        WT[0] = WT[4]; WT[1] = WT[5];
        WU[0] = WU[4]; WU[1] = WU[5];
        WV[0] = WV[4]; WV[1] = WV[5];
        HS[0] = HS[4]; HS[1] = HS[5];
        HT[0] = HT[4]; HT[1] = HT[5];
        HU[0] = HU[4]; HU[1] = HU[5];
        HV[0] = HV[4]; HV[1] = HV[5];
        #pragma unroll
        for (int k = 0; k < 4; ++k) {
            WS[2 + k] = PS[k]; WT[2 + k] = PT[k];
            WU[2 + k] = PU[k]; WV[2 + k] = PV[k];
            HS[2 + k] = QS[k]; HT[2 + k] = QT[k];
            HU[2 + k] = QU[k]; HV[2 + k] = QV[k];
        }
    }
}

extern "C" void kernel_launch(void* const* d_in, const int* in_sizes, int n_in,
                              void* d_out, int out_size) {
    const float* ss = (const float*)d_in[0];
    const float* sd = (const float*)d_in[1];
    const float* ds = (const float*)d_in[2];
    const float* dd = (const float*)d_in[3];
    const float* h  = (const float*)d_in[4];
    const float* g  = (const float*)d_in[5];
    float* out = (float*)d_out;

    dim3 grid(1, HH / RW, 4 * 64);   // (1, 8, 256) = 2048 blocks x 4 warps
    idwt2d<<<grid, NT>>>(ss, sd, ds, dd, h, g, out);
}